// round 1
// baseline (speedup 1.0000x reference)
#include <cuda_runtime.h>
#include <math.h>

// Problem constants
#define NB 8
#define RR 256
#define CI 64
#define CO 64
#define MODES 16
#define KX 32          // 2*MODES kx rows kept: {0..15} U {240..255}

// ---------------- device scratch (static, no allocs) ----------------
__device__ __align__(16) float g_Fx [64 * 256];          // [m][x]  m<32: cos, m>=32: -sin  (theta = 2*pi*kx*x/256)
__device__ __align__(16) float g_FxT[256 * 64];          // [x][m]  transpose for GEMM A
__device__ __align__(16) float g_Wy [256 * 16 * 2];      // [y][ky][{cos,sin}] theta = 2*pi*ky*y/256
__device__ __align__(16) float g_T  [NB * 64 * RR * CI]; // [b][m][y][c]   (33.5 MB)
__device__ __align__(16) float g_Gre[NB * KX * MODES * CI];
__device__ __align__(16) float g_Gim[NB * KX * MODES * CI];
__device__ __align__(16) float g_Hre[NB * CO * KX * MODES];
__device__ __align__(16) float g_Him[NB * CO * KX * MODES];
__device__ __align__(16) float g_Vre[NB * RR * CO * MODES]; // 8 MB
__device__ __align__(16) float g_Vim[NB * RR * CO * MODES]; // 8 MB

// ---------------- table init ----------------
__global__ void init_tables() {
    int t = blockIdx.x * blockDim.x + threadIdx.x;   // 0..16383
    if (t < 64 * 256) {
        int m = t >> 8, x = t & 255;
        int j = m & 31;
        int kx = (j < 16) ? j : (224 + j);           // j in [16,32) -> 240..255
        float s, c;
        sincospif((float)((kx * x) & 255) * (1.0f / 128.0f), &s, &c);
        float v = (m < 32) ? c : -s;
        g_Fx[m * 256 + x] = v;
        g_FxT[x * 64 + m] = v;
    }
    if (t < 256 * 16) {
        int y = t >> 4, ky = t & 15;
        float s, c;
        sincospif((float)((ky * y) & 255) * (1.0f / 128.0f), &s, &c);
        g_Wy[t * 2 + 0] = c;
        g_Wy[t * 2 + 1] = s;
    }
}

// ---------------- Stage A: x-direction partial DFT as GEMM ----------------
// T[b][m][yc] = sum_x FxT[x][m] * X[b][x][yc],  yc in [0,16384)
__global__ __launch_bounds__(256) void kA(const float* __restrict__ X) {
    int b  = blockIdx.y;
    int n0 = blockIdx.x * 64;
    __shared__ float As[32][64];
    __shared__ float Bs[32][64];
    const float* Xb = X + (size_t)b * RR * 16384;
    float* Tb = g_T + (size_t)b * 64 * 16384;
    int t  = threadIdx.x;
    int tn = (t & 15) * 4;
    int tm = (t >> 4) * 4;
    float acc[4][4] = {};
    for (int k0 = 0; k0 < 256; k0 += 32) {
        #pragma unroll
        for (int l = 0; l < 8; l++) {
            int e = t + l * 256;            // 0..2047
            int m = e & 63, k = e >> 6;
            As[k][m] = g_FxT[(k0 + k) * 64 + m];
        }
        #pragma unroll
        for (int l = 0; l < 2; l++) {
            int e = t + l * 256;            // float4 id 0..511
            int k = e >> 4, nv = (e & 15) * 4;
            *(float4*)&Bs[k][nv] =
                *(const float4*)&Xb[(size_t)(k0 + k) * 16384 + n0 + nv];
        }
        __syncthreads();
        #pragma unroll
        for (int k = 0; k < 32; k++) {
            float4 a4 = *(float4*)&As[k][tm];
            float4 b4 = *(float4*)&Bs[k][tn];
            acc[0][0] += a4.x * b4.x; acc[0][1] += a4.x * b4.y;
            acc[0][2] += a4.x * b4.z; acc[0][3] += a4.x * b4.w;
            acc[1][0] += a4.y * b4.x; acc[1][1] += a4.y * b4.y;
            acc[1][2] += a4.y * b4.z; acc[1][3] += a4.y * b4.w;
            acc[2][0] += a4.z * b4.x; acc[2][1] += a4.z * b4.y;
            acc[2][2] += a4.z * b4.z; acc[2][3] += a4.z * b4.w;
            acc[3][0] += a4.w * b4.x; acc[3][1] += a4.w * b4.y;
            acc[3][2] += a4.w * b4.z; acc[3][3] += a4.w * b4.w;
        }
        __syncthreads();
    }
    #pragma unroll
    for (int i = 0; i < 4; i++) {
        float4 v = make_float4(acc[i][0], acc[i][1], acc[i][2], acc[i][3]);
        *(float4*)&Tb[(size_t)(tm + i) * 16384 + n0 + tn] = v;
    }
}

// ---------------- Stage B: y-direction partial DFT (fold 1/256) ----------------
// G[b][j][ky][c] = (1/256) * sum_y (Tre + i Tim)[b][j][y][c] * e^{-i 2pi ky y / 256}
__global__ __launch_bounds__(256) void kB() {
    int j = blockIdx.x, b = blockIdx.y;
    __shared__ float Tre[32][64];
    __shared__ float Tim[32][64];
    __shared__ float Wys[256 * 16 * 2];   // 32KB
    int t = threadIdx.x;
    #pragma unroll
    for (int l = 0; l < 8; l++) {
        int e = (t + l * 256) * 4;        // float index, 8192 floats
        *(float4*)&Wys[e] = *(const float4*)&g_Wy[e];
    }
    const float* Tr = g_T + ((size_t)(b * 64 + j)      * 256) * 64;
    const float* Ti = g_T + ((size_t)(b * 64 + 32 + j) * 256) * 64;
    int c  = t & 63;
    int kg = t >> 6;                       // 0..3, handles ky = kg*4 + q
    float accR[4] = {}, accI[4] = {};
    for (int y0 = 0; y0 < 256; y0 += 32) {
        #pragma unroll
        for (int l = 0; l < 2; l++) {
            int e = t + l * 256;           // float4 id 0..511
            int yy = e >> 4, cv = (e & 15) * 4;
            *(float4*)&Tre[yy][cv] = *(const float4*)&Tr[(y0 + yy) * 64 + cv];
            *(float4*)&Tim[yy][cv] = *(const float4*)&Ti[(y0 + yy) * 64 + cv];
        }
        __syncthreads();
        for (int yy = 0; yy < 32; yy++) {
            float tr = Tre[yy][c], ti = Tim[yy][c];
            int y = y0 + yy;
            #pragma unroll
            for (int q = 0; q < 4; q++) {
                int ky = kg * 4 + q;
                float cc = Wys[(y * 16 + ky) * 2 + 0];
                float ss = Wys[(y * 16 + ky) * 2 + 1];
                accR[q] += tr * cc + ti * ss;   // (tr+i ti)*(c - i s)
                accI[q] += ti * cc - tr * ss;
            }
        }
        __syncthreads();
    }
    const float sc = 1.0f / 256.0f;
    #pragma unroll
    for (int q = 0; q < 4; q++) {
        int ky = kg * 4 + q;
        int idx = ((b * KX + j) * MODES + ky) * CI + c;
        g_Gre[idx] = accR[q] * sc;
        g_Gim[idx] = accI[q] * sc;
    }
}

// ---------------- Stage C: per-frequency complex channel mixing ----------------
// H[b][o][j][ky] = sum_i G[b][i] * w[i][o]   (complex)
__global__ __launch_bounds__(256) void kC(const float* __restrict__ fw0,
                                          const float* __restrict__ fw1) {
    int ky = blockIdx.x & 15, j = blockIdx.x >> 4;
    __shared__ float wr[64 * 64];
    __shared__ float wi[64 * 64];
    __shared__ float gr[8 * 64];
    __shared__ float gi[8 * 64];
    const float* fw = (j < 16) ? fw0 : fw1;
    int jm = j & 15;
    int t = threadIdx.x;
    #pragma unroll
    for (int l = 0; l < 16; l++) {
        int e = t + l * 256;               // 0..4095 : i = e>>6, o = e&63
        int i = e >> 6, o = e & 63;
        const float2 p = *(const float2*)&fw[((((size_t)i * 64 + o) * 16 + jm) * 16 + ky) * 2];
        wr[e] = p.x;
        wi[e] = p.y;
    }
    #pragma unroll
    for (int l = 0; l < 2; l++) {
        int e = t + l * 256;               // 0..511 : b = e>>6, i = e&63
        int b = e >> 6, i = e & 63;
        int gidx = ((b * KX + j) * MODES + ky) * CI + i;
        gr[e] = g_Gre[gidx];
        gi[e] = g_Gim[gidx];
    }
    __syncthreads();
    #pragma unroll
    for (int l = 0; l < 2; l++) {
        int p = t + l * 256;
        int b = p >> 6, o = p & 63;
        float hr = 0.f, hi = 0.f;
        #pragma unroll 8
        for (int i = 0; i < 64; i++) {
            float ar = gr[b * 64 + i], ai = gi[b * 64 + i];
            float br = wr[i * 64 + o], bi = wi[i * 64 + o];
            hr += ar * br - ai * bi;
            hi += ar * bi + ai * br;
        }
        int hidx = ((b * CO + o) * KX + j) * MODES + ky;
        g_Hre[hidx] = hr;
        g_Him[hidx] = hi;
    }
}

// ---------------- Stage D: inverse x-DFT (fold 1/256) ----------------
// V[b][x][o][ky] = (1/256) * sum_j H[b][o][j][ky] * e^{+i 2pi kx_j x / 256}
__global__ __launch_bounds__(256) void kD() {
    int o = blockIdx.x & 63, b = blockIdx.x >> 6;
    __shared__ __align__(16) float hr[KX * MODES];
    __shared__ __align__(16) float hi[KX * MODES];
    int t = threadIdx.x;
    int base = (b * CO + o) * KX * MODES;  // 512 per (b,o)
    hr[t]       = g_Hre[base + t];
    hi[t]       = g_Him[base + t];
    hr[t + 256] = g_Hre[base + t + 256];
    hi[t + 256] = g_Him[base + t + 256];
    __syncthreads();
    int x = t;
    float vr[16] = {}, vi[16] = {};
    for (int j = 0; j < 32; j++) {
        float c =  g_Fx[j * 256 + x];
        float s = -g_Fx[(32 + j) * 256 + x];
        #pragma unroll
        for (int kv = 0; kv < 4; kv++) {
            float4 ar = *(float4*)&hr[j * 16 + kv * 4];
            float4 ai = *(float4*)&hi[j * 16 + kv * 4];
            vr[kv*4+0] += ar.x * c - ai.x * s;  vi[kv*4+0] += ar.x * s + ai.x * c;
            vr[kv*4+1] += ar.y * c - ai.y * s;  vi[kv*4+1] += ar.y * s + ai.y * c;
            vr[kv*4+2] += ar.z * c - ai.z * s;  vi[kv*4+2] += ar.z * s + ai.z * c;
            vr[kv*4+3] += ar.w * c - ai.w * s;  vi[kv*4+3] += ar.w * s + ai.w * c;
        }
    }
    const float sc = 1.0f / 256.0f;
    size_t vbase = (((size_t)b * RR + x) * CO + o) * MODES;
    #pragma unroll
    for (int kv = 0; kv < 4; kv++) {
        float4 a = make_float4(vr[kv*4]*sc, vr[kv*4+1]*sc, vr[kv*4+2]*sc, vr[kv*4+3]*sc);
        float4 bb = make_float4(vi[kv*4]*sc, vi[kv*4+1]*sc, vi[kv*4+2]*sc, vi[kv*4+3]*sc);
        *(float4*)&g_Vre[vbase + kv * 4] = a;
        *(float4*)&g_Vim[vbase + kv * 4] = bb;
    }
}

// ---------------- Stage E: inverse y-DFT + residual GEMM + SiLU ----------------
// out[b][x][y][o] = silu( sum_ky f(ky)*(Vr*cos - Vi*sin) + b_res[o] + sum_i X[b][x][y][i]*W[i][o] )
__global__ __launch_bounds__(256) void kE(const float* __restrict__ X,
                                          const float* __restrict__ Wres,
                                          const float* __restrict__ bres,
                                          float* __restrict__ out) {
    int x = blockIdx.x & 255, b = blockIdx.x >> 8;
    __shared__ __align__(16) float Xs[128 * 64];   // 32KB, half-row chunk
    __shared__ __align__(16) float Ws[64 * 64];    // 16KB
    int t = threadIdx.x;
    #pragma unroll
    for (int l = 0; l < 16; l++) Ws[t + l * 256] = Wres[t + l * 256];

    int o  = t & 63;
    int yq = t >> 6;                               // 0..3
    // register-cache the W column for this thread's o
    float wv[64];
    float vr[16], vi[16];
    {
        size_t vbase = (((size_t)b * RR + x) * CO + o) * MODES;
        #pragma unroll
        for (int kv = 0; kv < 4; kv++) {
            float4 a = *(const float4*)&g_Vre[vbase + kv * 4];
            float4 c = *(const float4*)&g_Vim[vbase + kv * 4];
            vr[kv*4+0]=a.x; vr[kv*4+1]=a.y; vr[kv*4+2]=a.z; vr[kv*4+3]=a.w;
            vi[kv*4+0]=c.x; vi[kv*4+1]=c.y; vi[kv*4+2]=c.z; vi[kv*4+3]=c.w;
        }
    }
    float bv = bres[o];
    __syncthreads();
    #pragma unroll
    for (int i = 0; i < 64; i++) wv[i] = Ws[i * 64 + o];

    const float* Xrow = X   + ((size_t)(b * RR + x)) * 256 * 64;
    float*       orow = out + ((size_t)(b * RR + x)) * 256 * 64;

    for (int ch = 0; ch < 2; ch++) {
        int ybase = ch * 128;
        __syncthreads();
        #pragma unroll
        for (int l = 0; l < 8; l++) {
            int e = (t + l * 256) * 4;             // 8192 floats
            *(float4*)&Xs[e] = *(const float4*)&Xrow[ybase * 64 + e];
        }
        __syncthreads();
        for (int n = 0; n < 32; n++) {
            int yl = yq * 32 + n;                  // within chunk
            int y  = ybase + yl;
            // inverse y-DFT real part
            float inv = 0.f;
            #pragma unroll
            for (int ky = 0; ky < 16; ky++) {
                float2 cs = *(const float2*)&g_Wy[(y * 16 + ky) * 2];
                float f = (ky == 0) ? 1.0f : 2.0f;
                inv += f * (vr[ky] * cs.x - vi[ky] * cs.y);
            }
            // residual matvec
            float acc = bv;
            #pragma unroll
            for (int i = 0; i < 64; i += 4) {
                float4 xv = *(float4*)&Xs[yl * 64 + i];
                acc += xv.x * wv[i] + xv.y * wv[i+1] + xv.z * wv[i+2] + xv.w * wv[i+3];
            }
            float v = acc + inv;
            float sig = 1.0f / (1.0f + __expf(-v));
            orow[y * 64 + o] = v * sig;
        }
    }
}

// ---------------- launch ----------------
extern "C" void kernel_launch(void* const* d_in, const int* in_sizes, int n_in,
                              void* d_out, int out_size) {
    const float* X    = (const float*)d_in[0];
    const float* Wres = (const float*)d_in[1];
    const float* bres = (const float*)d_in[2];
    const float* fw0  = (const float*)d_in[3];
    const float* fw1  = (const float*)d_in[4];
    float* out = (float*)d_out;

    init_tables<<<64, 256>>>();
    kA<<<dim3(256, NB), 256>>>(X);
    kB<<<dim3(KX, NB), 256>>>();
    kC<<<KX * MODES, 256>>>(fw0, fw1);
    kD<<<NB * CO, 256>>>();
    kE<<<NB * RR, 256>>>(X, Wres, bres, out);
}